// round 2
// baseline (speedup 1.0000x reference)
#include <cuda_runtime.h>

#define BATCH 4096
#define T_LEN 256
#define I1 38
#define H1 50
#define H2 15
#define NC 14
#define G1 200        // 4*H1 gates, layer 1
#define G2 60         // 4*H2 gates, layer 2
#define BB 8          // batch rows per CTA
#define THREADS 288
#define L2_BASE 224   // L2 gate threads occupy [224, 284) -> separate warps from L1

// Padded row widths for float4 smem loads (pads are zeroed once, never rewritten)
#define XP 40   // I1=38 -> 40
#define HP1 52  // H1=50 -> 52
#define HP2 16  // H2=15 -> 16

struct __align__(16) Smem {
    float x[2][BB][XP];        // double-buffered input tile
    float h1[BB][HP1];         // layer-1 hidden state (current)
    float gates1[BB][G1];      // layer-1 pre-activation gates
    float h2[BB][HP2];         // layer-2 hidden state
    float gates2[BB][64];      // layer-2 pre-activation gates (padded 60->64)
};

__device__ __forceinline__ float sigm(float v) {
    // 1/(1+e^-v); e^inf -> inf, fdividef -> 0 : correct saturation
    return __fdividef(1.0f, 1.0f + __expf(-v));
}
__device__ __forceinline__ float tanh_f(float v) {
    // overflow-safe: e = exp(-2|v|) <= 1
    float a = fabsf(v);
    float e = __expf(-2.0f * a);
    float t = __fdividef(1.0f - e, 1.0f + e);
    return copysignf(t, v);
}

__global__ void __launch_bounds__(THREADS)
lstm2_kernel(const float* __restrict__ x,
             const float* __restrict__ w_ih1, const float* __restrict__ w_hh1,
             const float* __restrict__ b_ih1, const float* __restrict__ b_hh1,
             const float* __restrict__ w_ih2, const float* __restrict__ w_hh2,
             const float* __restrict__ b_ih2, const float* __restrict__ b_hh2,
             const float* __restrict__ w_fc,  const float* __restrict__ b_fc,
             float* __restrict__ out)
{
    __shared__ Smem sm;
    const int tid   = threadIdx.x;
    const int bbase = blockIdx.x * BB;

    // ---- zero smem (state + pads; pads are never rewritten afterwards) ----
    for (int i = tid; i < (int)(sizeof(Smem) / 4); i += THREADS)
        ((float*)&sm)[i] = 0.0f;

    const bool isL1 = (tid < G1);
    const bool isL2 = (tid >= L2_BASE) && (tid < L2_BASE + G2);

    // ---- per-thread weight registers (shared array between the two roles) ----
    float wreg[92];
    #pragma unroll
    for (int k = 0; k < 92; k++) wreg[k] = 0.0f;

    float bias = 0.0f;
    if (isL1) {
        const int g = tid;
        #pragma unroll
        for (int k = 0; k < I1; k++) wreg[k] = w_ih1[g * I1 + k];        // [0..37]
        #pragma unroll
        for (int k = 0; k < H1; k++) wreg[XP + k] = w_hh1[g * H1 + k];   // [40..89]
        bias = b_ih1[g] + b_hh1[g];
    } else if (isL2) {
        const int g2 = tid - L2_BASE;
        #pragma unroll
        for (int k = 0; k < H1; k++) wreg[k] = w_ih2[g2 * H1 + k];       // [0..49]
        #pragma unroll
        for (int k = 0; k < H2; k++) wreg[HP1 + k] = w_hh2[g2 * H2 + k]; // [52..66]
        bias = b_ih2[g2] + b_hh2[g2];
    }

    // update-thread mappings (hoisted)
    const int u1  = isL1 ? (tid % H1) : 0;          // L1 unit
    const int b1  = isL1 ? (tid / H1) : 0;          // L1 batch 0..3 (+4 for 2nd item)
    const int u2  = isL2 ? ((tid - L2_BASE) % H2) : 0;
    const int b2  = isL2 ? ((tid - L2_BASE) / H2) : 0;
    float c1a = 0.0f, c1b = 0.0f;   // L1 cell state (regs)
    float c2a = 0.0f, c2b = 0.0f;   // L2 cell state (regs)

    // ---- preload x(t=0) ----
    __syncthreads();
    for (int i = tid; i < BB * I1; i += THREADS) {
        int bb = i / I1, k = i - bb * I1;
        sm.x[0][bb][k] = x[((long)(bbase + bb) * T_LEN + 0) * I1 + k];
    }
    __syncthreads();

    // L2 gate compute (used in mainloop for step t-1 and in epilogue for t=T-1)
    auto l2_gates = [&]() {
        const int g2 = tid - L2_BASE;
        float acc[BB];
        #pragma unroll
        for (int bb = 0; bb < BB; bb++) acc[bb] = bias;
        #pragma unroll
        for (int k4 = 0; k4 < HP1 / 4; k4++) {      // h1 part, 13 float4s
            #pragma unroll
            for (int bb = 0; bb < BB; bb++) {
                float4 v = *((const float4*)&sm.h1[bb][4 * k4]);
                acc[bb] = fmaf(v.x, wreg[4 * k4 + 0], acc[bb]);
                acc[bb] = fmaf(v.y, wreg[4 * k4 + 1], acc[bb]);
                acc[bb] = fmaf(v.z, wreg[4 * k4 + 2], acc[bb]);
                acc[bb] = fmaf(v.w, wreg[4 * k4 + 3], acc[bb]);
            }
        }
        #pragma unroll
        for (int k4 = 0; k4 < HP2 / 4; k4++) {      // h2 part, 4 float4s
            #pragma unroll
            for (int bb = 0; bb < BB; bb++) {
                float4 v = *((const float4*)&sm.h2[bb][4 * k4]);
                acc[bb] = fmaf(v.x, wreg[HP1 + 4 * k4 + 0], acc[bb]);
                acc[bb] = fmaf(v.y, wreg[HP1 + 4 * k4 + 1], acc[bb]);
                acc[bb] = fmaf(v.z, wreg[HP1 + 4 * k4 + 2], acc[bb]);
                acc[bb] = fmaf(v.w, wreg[HP1 + 4 * k4 + 3], acc[bb]);
            }
        }
        #pragma unroll
        for (int bb = 0; bb < BB; bb++) sm.gates2[bb][g2] = acc[bb];
    };

    auto l2_update = [&]() {
        {
            float ig = sigm(sm.gates2[b2][u2]);
            float fg = sigm(sm.gates2[b2][H2 + u2]);
            float gg = tanh_f(sm.gates2[b2][2 * H2 + u2]);
            float og = sigm(sm.gates2[b2][3 * H2 + u2]);
            c2a = fg * c2a + ig * gg;
            sm.h2[b2][u2] = og * tanh_f(c2a);
        }
        {
            int bb = b2 + 4;
            float ig = sigm(sm.gates2[bb][u2]);
            float fg = sigm(sm.gates2[bb][H2 + u2]);
            float gg = tanh_f(sm.gates2[bb][2 * H2 + u2]);
            float og = sigm(sm.gates2[bb][3 * H2 + u2]);
            c2b = fg * c2b + ig * gg;
            sm.h2[bb][u2] = og * tanh_f(c2b);
        }
    };

    // =================== main recurrence ===================
    for (int t = 0; t < T_LEN; ++t) {
        const int buf = t & 1;

        // ---- Phase A: L1 gates(t) || L2 gates(t-1) ----
        if (isL1) {
            float acc[BB];
            #pragma unroll
            for (int bb = 0; bb < BB; bb++) acc[bb] = bias;
            #pragma unroll
            for (int k4 = 0; k4 < XP / 4; k4++) {   // input part, 10 float4s
                #pragma unroll
                for (int bb = 0; bb < BB; bb++) {
                    float4 v = *((const float4*)&sm.x[buf][bb][4 * k4]);
                    acc[bb] = fmaf(v.x, wreg[4 * k4 + 0], acc[bb]);
                    acc[bb] = fmaf(v.y, wreg[4 * k4 + 1], acc[bb]);
                    acc[bb] = fmaf(v.z, wreg[4 * k4 + 2], acc[bb]);
                    acc[bb] = fmaf(v.w, wreg[4 * k4 + 3], acc[bb]);
                }
            }
            #pragma unroll
            for (int k4 = 0; k4 < HP1 / 4; k4++) {  // recurrent part, 13 float4s
                #pragma unroll
                for (int bb = 0; bb < BB; bb++) {
                    float4 v = *((const float4*)&sm.h1[bb][4 * k4]);
                    acc[bb] = fmaf(v.x, wreg[XP + 4 * k4 + 0], acc[bb]);
                    acc[bb] = fmaf(v.y, wreg[XP + 4 * k4 + 1], acc[bb]);
                    acc[bb] = fmaf(v.z, wreg[XP + 4 * k4 + 2], acc[bb]);
                    acc[bb] = fmaf(v.w, wreg[XP + 4 * k4 + 3], acc[bb]);
                }
            }
            #pragma unroll
            for (int bb = 0; bb < BB; bb++) sm.gates1[bb][tid] = acc[bb];
        } else if (isL2 && t > 0) {
            l2_gates();   // step t-1
        }
        __syncthreads();

        // ---- Phase B: L1 update(t) || L2 update(t-1) || prefetch x(t+1) ----
        if (isL1) {
            {
                float ig = sigm(sm.gates1[b1][u1]);
                float fg = sigm(sm.gates1[b1][H1 + u1]);
                float gg = tanh_f(sm.gates1[b1][2 * H1 + u1]);
                float og = sigm(sm.gates1[b1][3 * H1 + u1]);
                c1a = fg * c1a + ig * gg;
                sm.h1[b1][u1] = og * tanh_f(c1a);
            }
            {
                int bb = b1 + 4;
                float ig = sigm(sm.gates1[bb][u1]);
                float fg = sigm(sm.gates1[bb][H1 + u1]);
                float gg = tanh_f(sm.gates1[bb][2 * H1 + u1]);
                float og = sigm(sm.gates1[bb][3 * H1 + u1]);
                c1b = fg * c1b + ig * gg;
                sm.h1[bb][u1] = og * tanh_f(c1b);
            }
        } else if (isL2 && t > 0) {
            l2_update();  // step t-1
        }
        if (t + 1 < T_LEN) {
            for (int i = tid; i < BB * I1; i += THREADS) {
                int bb = i / I1, k = i - bb * I1;
                sm.x[buf ^ 1][bb][k] =
                    x[((long)(bbase + bb) * T_LEN + (t + 1)) * I1 + k];
            }
        }
        __syncthreads();
    }

    // =================== epilogue: L2 step t = T-1, then FC ===================
    if (isL2) l2_gates();        // uses h1[T-1], h2[T-2]
    __syncthreads();
    if (isL2) l2_update();       // h2[T-1]
    __syncthreads();

    if (tid < BB * NC) {
        int bb = tid / NC, nc = tid - bb * NC;
        float s = b_fc[nc];
        #pragma unroll
        for (int k = 0; k < H2; k++) s = fmaf(sm.h2[bb][k], w_fc[nc * H2 + k], s);
        out[(long)(bbase + bb) * NC + nc] = s;
    }
}

extern "C" void kernel_launch(void* const* d_in, const int* in_sizes, int n_in,
                              void* d_out, int out_size)
{
    const float* x     = (const float*)d_in[0];
    const float* w_ih1 = (const float*)d_in[1];
    const float* w_hh1 = (const float*)d_in[2];
    const float* b_ih1 = (const float*)d_in[3];
    const float* b_hh1 = (const float*)d_in[4];
    const float* w_ih2 = (const float*)d_in[5];
    const float* w_hh2 = (const float*)d_in[6];
    const float* b_ih2 = (const float*)d_in[7];
    const float* b_hh2 = (const float*)d_in[8];
    const float* w_fc  = (const float*)d_in[9];
    const float* b_fc  = (const float*)d_in[10];
    float* out = (float*)d_out;

    lstm2_kernel<<<BATCH / BB, THREADS>>>(x, w_ih1, w_hh1, b_ih1, b_hh1,
                                          w_ih2, w_hh2, b_ih2, b_hh2,
                                          w_fc, b_fc, out);
}

// round 8
// speedup vs baseline: 1.2928x; 1.2928x over previous
#include <cuda_runtime.h>

#define BATCH 4096
#define T_LEN 256
#define I1 38
#define H1 50
#define H2 15
#define NC 14
#define G1 200        // 4*H1 gates, layer 1
#define G2 60         // 4*H2 gates, layer 2
#define BB 8          // batch rows per CTA
#define THREADS 288
#define L2_BASE 224   // L2 gate threads occupy [224, 284) -> separate warps from L1

// Padded row widths for 16B smem loads (pads zeroed once, never rewritten)
#define XP 40   // I1=38 -> 40   (20 f32 pairs)
#define HP1 52  // H1=50 -> 52   (26 f32 pairs)
#define HP2 16  // H2=15 -> 16   (8 f32 pairs)
#define NXEL (BB * I1)   // 304 x elements per step per CTA

typedef unsigned long long ull;

struct __align__(16) Smem {
    float x[2][BB][XP];        // double-buffered input tile
    float h1[BB][HP1];         // layer-1 hidden state
    float gates1[BB][G1];      // layer-1 pre-activation gates
    float h2[BB][HP2];         // layer-2 hidden state
    float gates2[BB][64];      // layer-2 pre-activation gates (padded 60->64)
};

__device__ __forceinline__ ull pack2(float lo, float hi) {
    ull r;
    asm("mov.b64 %0, {%1, %2};" : "=l"(r) : "f"(lo), "f"(hi));
    return r;
}
__device__ __forceinline__ void unpack2(ull p, float& lo, float& hi) {
    asm("mov.b64 {%0, %1}, %2;" : "=f"(lo), "=f"(hi) : "l"(p));
}
// packed dual FMA on the fp32 pipe (FFMA2) — only reachable via PTX f32x2
__device__ __forceinline__ ull ffma2(ull a, ull b, ull c) {
    ull d;
    asm("fma.rn.f32x2 %0, %1, %2, %3;" : "=l"(d) : "l"(a), "l"(b), "l"(c));
    return d;
}

__device__ __forceinline__ float sigm(float v) {
    return __fdividef(1.0f, 1.0f + __expf(-v));   // saturates correctly at +-inf
}
__device__ __forceinline__ float tanh_f(float v) {
    float a = fabsf(v);
    float e = __expf(-2.0f * a);                  // <= 1, overflow-safe
    float t = __fdividef(1.0f - e, 1.0f + e);
    return copysignf(t, v);
}

__global__ void __launch_bounds__(THREADS)
lstm2_kernel(const float* __restrict__ x,
             const float* __restrict__ w_ih1, const float* __restrict__ w_hh1,
             const float* __restrict__ b_ih1, const float* __restrict__ b_hh1,
             const float* __restrict__ w_ih2, const float* __restrict__ w_hh2,
             const float* __restrict__ b_ih2, const float* __restrict__ b_hh2,
             const float* __restrict__ w_fc,  const float* __restrict__ b_fc,
             float* __restrict__ out)
{
    __shared__ Smem sm;
    const int tid   = threadIdx.x;
    const int bbase = blockIdx.x * BB;

    // ---- zero smem (state + pads; pads never rewritten afterwards) ----
    for (int i = tid; i < (int)(sizeof(Smem) / 4); i += THREADS)
        ((float*)&sm)[i] = 0.0f;

    const bool isL1 = (tid < G1);
    const bool isL2 = (tid >= L2_BASE) && (tid < L2_BASE + G2);

    // ---- per-thread packed weight pairs (roles share the array) ----
    // L1: pairs [0..19] = w_ih row (XP), pairs [20..45] = w_hh row (HP1)
    // L2: pairs [0..25] = w_ih2 row over HP1, pairs [26..33] = w_hh2 row over HP2
    ull wreg2[46];
    #pragma unroll
    for (int k = 0; k < 46; k++) wreg2[k] = 0ull;

    float bias = 0.0f;
    if (isL1) {
        const int g = tid;
        #pragma unroll
        for (int p = 0; p < XP / 2; p++) {
            int e = 2 * p;
            float lo = (e     < I1) ? w_ih1[g * I1 + e]     : 0.0f;
            float hi = (e + 1 < I1) ? w_ih1[g * I1 + e + 1] : 0.0f;
            wreg2[p] = pack2(lo, hi);
        }
        #pragma unroll
        for (int p = 0; p < HP1 / 2; p++) {
            int e = 2 * p;
            float lo = (e     < H1) ? w_hh1[g * H1 + e]     : 0.0f;
            float hi = (e + 1 < H1) ? w_hh1[g * H1 + e + 1] : 0.0f;
            wreg2[XP / 2 + p] = pack2(lo, hi);
        }
        bias = b_ih1[g] + b_hh1[g];
    } else if (isL2) {
        const int g2 = tid - L2_BASE;
        #pragma unroll
        for (int p = 0; p < HP1 / 2; p++) {
            int e = 2 * p;
            float lo = (e     < H1) ? w_ih2[g2 * H1 + e]     : 0.0f;
            float hi = (e + 1 < H1) ? w_ih2[g2 * H1 + e + 1] : 0.0f;
            wreg2[p] = pack2(lo, hi);
        }
        #pragma unroll
        for (int p = 0; p < HP2 / 2; p++) {
            int e = 2 * p;
            float lo = (e     < H2) ? w_hh2[g2 * H2 + e]     : 0.0f;
            float hi = (e + 1 < H2) ? w_hh2[g2 * H2 + e + 1] : 0.0f;
            wreg2[HP1 / 2 + p] = pack2(lo, hi);
        }
        bias = b_ih2[g2] + b_hh2[g2];
    }

    // update-thread mappings
    const int u1 = isL1 ? (tid % H1) : 0;
    const int b1 = isL1 ? (tid / H1) : 0;               // 0..3 (+4 for second item)
    const int u2 = isL2 ? ((tid - L2_BASE) % H2) : 0;
    const int b2 = isL2 ? ((tid - L2_BASE) / H2) : 0;
    float c1a = 0.0f, c1b = 0.0f;
    float c2a = 0.0f, c2b = 0.0f;

    // ---- x register prefetch lanes: thread covers flat idx tid and tid+THREADS ----
    const int xi0 = tid;                 // tid < 288 < NXEL=304: always valid
    const int xb0 = xi0 / I1, xk0 = xi0 - xb0 * I1;
    const bool hasX1 = (tid + THREADS) < NXEL;     // 16 threads
    const int xi1 = tid + THREADS;
    const int xb1 = xi1 / I1, xk1 = xi1 - xb1 * I1;

    float xr0 = 0.0f, xr1 = 0.0f;

    // ---- prologue: x(0) -> smem buf 0; xr <- x(1) ----
    __syncthreads();   // smem zero done
    {
        sm.x[0][xb0][xk0] = x[((long)(bbase + xb0) * T_LEN + 0) * I1 + xk0];
        if (hasX1)
            sm.x[0][xb1][xk1] = x[((long)(bbase + xb1) * T_LEN + 0) * I1 + xk1];
        if (T_LEN > 1) {
            xr0 = x[((long)(bbase + xb0) * T_LEN + 1) * I1 + xk0];
            if (hasX1) xr1 = x[((long)(bbase + xb1) * T_LEN + 1) * I1 + xk1];
        }
    }
    __syncthreads();

    // L2 gate compute (mainloop: step t-1; epilogue: step T-1)
    auto l2_gates = [&]() {
        const int g2 = tid - L2_BASE;
        ull acc[BB];
        #pragma unroll
        for (int bb = 0; bb < BB; bb++) acc[bb] = pack2(bias, 0.0f);
        #pragma unroll
        for (int k4 = 0; k4 < HP1 / 4; k4++) {      // h1 part: 13 LDS.128
            #pragma unroll
            for (int bb = 0; bb < BB; bb++) {
                ulonglong2 v = *((const ulonglong2*)&sm.h1[bb][4 * k4]);
                acc[bb] = ffma2(v.x, wreg2[2 * k4],     acc[bb]);
                acc[bb] = ffma2(v.y, wreg2[2 * k4 + 1], acc[bb]);
            }
        }
        #pragma unroll
        for (int k4 = 0; k4 < HP2 / 4; k4++) {      // h2 part: 4 LDS.128
            #pragma unroll
            for (int bb = 0; bb < BB; bb++) {
                ulonglong2 v = *((const ulonglong2*)&sm.h2[bb][4 * k4]);
                acc[bb] = ffma2(v.x, wreg2[HP1 / 2 + 2 * k4],     acc[bb]);
                acc[bb] = ffma2(v.y, wreg2[HP1 / 2 + 2 * k4 + 1], acc[bb]);
            }
        }
        #pragma unroll
        for (int bb = 0; bb < BB; bb++) {
            float lo, hi; unpack2(acc[bb], lo, hi);
            sm.gates2[bb][g2] = lo + hi;
        }
    };

    auto l2_update = [&]() {
        {
            float ig = sigm(sm.gates2[b2][u2]);
            float fg = sigm(sm.gates2[b2][H2 + u2]);
            float gg = tanh_f(sm.gates2[b2][2 * H2 + u2]);
            float og = sigm(sm.gates2[b2][3 * H2 + u2]);
            c2a = fg * c2a + ig * gg;
            sm.h2[b2][u2] = og * tanh_f(c2a);
        }
        {
            int bb = b2 + 4;
            float ig = sigm(sm.gates2[bb][u2]);
            float fg = sigm(sm.gates2[bb][H2 + u2]);
            float gg = tanh_f(sm.gates2[bb][2 * H2 + u2]);
            float og = sigm(sm.gates2[bb][3 * H2 + u2]);
            c2b = fg * c2b + ig * gg;
            sm.h2[bb][u2] = og * tanh_f(c2b);
        }
    };

    // =================== main recurrence ===================
    for (int t = 0; t < T_LEN; ++t) {
        const int buf = t & 1;

        // ---- top of phase A: commit x(t+1) regs -> smem buf^1 (buffer idle
        //      since last step's barrier), then issue LDG for x(t+2) ----
        if (t + 1 < T_LEN) {
            sm.x[buf ^ 1][xb0][xk0] = xr0;
            if (hasX1) sm.x[buf ^ 1][xb1][xk1] = xr1;
        }
        if (t + 2 < T_LEN) {
            xr0 = x[((long)(bbase + xb0) * T_LEN + (t + 2)) * I1 + xk0];
            if (hasX1) xr1 = x[((long)(bbase + xb1) * T_LEN + (t + 2)) * I1 + xk1];
        }

        // ---- Phase A: L1 gates(t) || L2 gates(t-1) ----
        if (isL1) {
            ull acc[BB];
            #pragma unroll
            for (int bb = 0; bb < BB; bb++) acc[bb] = pack2(bias, 0.0f);
            #pragma unroll
            for (int k4 = 0; k4 < XP / 4; k4++) {   // input part: 10 LDS.128
                #pragma unroll
                for (int bb = 0; bb < BB; bb++) {
                    ulonglong2 v = *((const ulonglong2*)&sm.x[buf][bb][4 * k4]);
                    acc[bb] = ffma2(v.x, wreg2[2 * k4],     acc[bb]);
                    acc[bb] = ffma2(v.y, wreg2[2 * k4 + 1], acc[bb]);
                }
            }
            #pragma unroll
            for (int k4 = 0; k4 < HP1 / 4; k4++) {  // recurrent part: 13 LDS.128
                #pragma unroll
                for (int bb = 0; bb < BB; bb++) {
                    ulonglong2 v = *((const ulonglong2*)&sm.h1[bb][4 * k4]);
                    acc[bb] = ffma2(v.x, wreg2[XP / 2 + 2 * k4],     acc[bb]);
                    acc[bb] = ffma2(v.y, wreg2[XP / 2 + 2 * k4 + 1], acc[bb]);
                }
            }
            #pragma unroll
            for (int bb = 0; bb < BB; bb++) {
                float lo, hi; unpack2(acc[bb], lo, hi);
                sm.gates1[bb][tid] = lo + hi;
            }
        } else if (isL2 && t > 0) {
            l2_gates();   // step t-1
        }
        __syncthreads();

        // ---- Phase B: L1 update(t) || L2 update(t-1) ----
        if (isL1) {
            {
                float ig = sigm(sm.gates1[b1][u1]);
                float fg = sigm(sm.gates1[b1][H1 + u1]);
                float gg = tanh_f(sm.gates1[b1][2 * H1 + u1]);
                float og = sigm(sm.gates1[b1][3 * H1 + u1]);
                c1a = fg * c1a + ig * gg;
                sm.h1[b1][u1] = og * tanh_f(c1a);
            }
            {
                int bb = b1 + 4;
                float ig = sigm(sm.gates1[bb][u1]);
                float fg = sigm(sm.gates1[bb][H1 + u1]);
                float gg = tanh_f(sm.gates1[bb][2 * H1 + u1]);
                float og = sigm(sm.gates1[bb][3 * H1 + u1]);
                c1b = fg * c1b + ig * gg;
                sm.h1[bb][u1] = og * tanh_f(c1b);
            }
        } else if (isL2 && t > 0) {
            l2_update();  // step t-1
        }
        __syncthreads();
    }

    // =================== epilogue: L2 step T-1, then FC ===================
    if (isL2) l2_gates();        // uses h1[T-1], h2[T-2]
    __syncthreads();
    if (isL2) l2_update();       // h2[T-1]
    __syncthreads();

    if (tid < BB * NC) {
        int bb = tid / NC, nc = tid - bb * NC;
        float s = b_fc[nc];
        #pragma unroll
        for (int k = 0; k < H2; k++) s = fmaf(sm.h2[bb][k], w_fc[nc * H2 + k], s);
        out[(long)(bbase + bb) * NC + nc] = s;
    }
}

extern "C" void kernel_launch(void* const* d_in, const int* in_sizes, int n_in,
                              void* d_out, int out_size)
{
    const float* x     = (const float*)d_in[0];
    const float* w_ih1 = (const float*)d_in[1];
    const float* w_hh1 = (const float*)d_in[2];
    const float* b_ih1 = (const float*)d_in[3];
    const float* b_hh1 = (const float*)d_in[4];
    const float* w_ih2 = (const float*)d_in[5];
    const float* w_hh2 = (const float*)d_in[6];
    const float* b_ih2 = (const float*)d_in[7];
    const float* b_hh2 = (const float*)d_in[8];
    const float* w_fc  = (const float*)d_in[9];
    const float* b_fc  = (const float*)d_in[10];
    float* out = (float*)d_out;

    lstm2_kernel<<<BATCH / BB, THREADS>>>(x, w_ih1, w_hh1, b_ih1, b_hh1,
                                          w_ih2, w_hh2, b_ih2, b_hh2,
                                          w_fc, b_fc, out);
}

// round 9
// speedup vs baseline: 1.3766x; 1.0648x over previous
#include <cuda_runtime.h>

#define BATCH 4096
#define T_LEN 256
#define I1 38
#define H1 50
#define H2 15
#define NC 14
#define G1 200        // 4*H1 gates, layer 1
#define G2 60         // 4*H2 gates, layer 2
#define BB 16         // batch rows per CTA (retiled 8 -> 16; grid 512 -> 256)
#define CHUNK 8       // bb processed per register-chunk in gate loops
#define THREADS 288
#define L2_BASE 224   // L2 gate threads occupy [224, 284) -> separate warps from L1

// Padded row widths for 16B smem loads (pads zeroed once, never rewritten)
#define XP 40   // I1=38 -> 40   (20 f32 pairs)
#define HP1 52  // H1=50 -> 52   (26 f32 pairs)
#define HP2 16  // H2=15 -> 16   (8 f32 pairs)
#define NXEL (BB * I1)   // 608 x elements per step per CTA

typedef unsigned long long ull;

struct __align__(16) Smem {
    float x[2][BB][XP];        // double-buffered input tile      (5.1 KB)
    float h1[BB][HP1];         // layer-1 hidden state            (3.3 KB)
    float gates1[BB][G1];      // layer-1 pre-activation gates    (12.8 KB)
    float h2[BB][HP2];         // layer-2 hidden state            (1.0 KB)
    float gates2[BB][64];      // layer-2 gates (padded 60->64)   (4.1 KB)
};

__device__ __forceinline__ ull pack2(float lo, float hi) {
    ull r;
    asm("mov.b64 %0, {%1, %2};" : "=l"(r) : "f"(lo), "f"(hi));
    return r;
}
__device__ __forceinline__ void unpack2(ull p, float& lo, float& hi) {
    asm("mov.b64 {%0, %1}, %2;" : "=f"(lo), "=f"(hi) : "l"(p));
}
// packed dual FMA on the fp32 pipe (FFMA2) — only reachable via PTX f32x2
__device__ __forceinline__ ull ffma2(ull a, ull b, ull c) {
    ull d;
    asm("fma.rn.f32x2 %0, %1, %2, %3;" : "=l"(d) : "l"(a), "l"(b), "l"(c));
    return d;
}

__device__ __forceinline__ float sigm(float v) {
    return __fdividef(1.0f, 1.0f + __expf(-v));   // saturates correctly at +-inf
}
__device__ __forceinline__ float tanh_f(float v) {
    float a = fabsf(v);
    float e = __expf(-2.0f * a);                  // <= 1, overflow-safe
    float t = __fdividef(1.0f - e, 1.0f + e);
    return copysignf(t, v);
}

__global__ void __launch_bounds__(THREADS)
lstm2_kernel(const float* __restrict__ x,
             const float* __restrict__ w_ih1, const float* __restrict__ w_hh1,
             const float* __restrict__ b_ih1, const float* __restrict__ b_hh1,
             const float* __restrict__ w_ih2, const float* __restrict__ w_hh2,
             const float* __restrict__ b_ih2, const float* __restrict__ b_hh2,
             const float* __restrict__ w_fc,  const float* __restrict__ b_fc,
             float* __restrict__ out)
{
    __shared__ Smem sm;
    const int tid   = threadIdx.x;
    const int bbase = blockIdx.x * BB;

    // ---- zero smem (state + pads; pads never rewritten afterwards) ----
    for (int i = tid; i < (int)(sizeof(Smem) / 4); i += THREADS)
        ((float*)&sm)[i] = 0.0f;

    const bool isL1 = (tid < G1);
    const bool isL2 = (tid >= L2_BASE) && (tid < L2_BASE + G2);

    // ---- per-thread packed weight pairs (roles share the array) ----
    ull wreg2[46];
    #pragma unroll
    for (int k = 0; k < 46; k++) wreg2[k] = 0ull;

    float bias = 0.0f;
    if (isL1) {
        const int g = tid;
        #pragma unroll
        for (int p = 0; p < XP / 2; p++) {
            int e = 2 * p;
            float lo = (e     < I1) ? w_ih1[g * I1 + e]     : 0.0f;
            float hi = (e + 1 < I1) ? w_ih1[g * I1 + e + 1] : 0.0f;
            wreg2[p] = pack2(lo, hi);
        }
        #pragma unroll
        for (int p = 0; p < HP1 / 2; p++) {
            int e = 2 * p;
            float lo = (e     < H1) ? w_hh1[g * H1 + e]     : 0.0f;
            float hi = (e + 1 < H1) ? w_hh1[g * H1 + e + 1] : 0.0f;
            wreg2[XP / 2 + p] = pack2(lo, hi);
        }
        bias = b_ih1[g] + b_hh1[g];
    } else if (isL2) {
        const int g2 = tid - L2_BASE;
        #pragma unroll
        for (int p = 0; p < HP1 / 2; p++) {
            int e = 2 * p;
            float lo = (e     < H1) ? w_ih2[g2 * H1 + e]     : 0.0f;
            float hi = (e + 1 < H1) ? w_ih2[g2 * H1 + e + 1] : 0.0f;
            wreg2[p] = pack2(lo, hi);
        }
        #pragma unroll
        for (int p = 0; p < HP2 / 2; p++) {
            int e = 2 * p;
            float lo = (e     < H2) ? w_hh2[g2 * H2 + e]     : 0.0f;
            float hi = (e + 1 < H2) ? w_hh2[g2 * H2 + e + 1] : 0.0f;
            wreg2[HP1 / 2 + p] = pack2(lo, hi);
        }
        bias = b_ih2[g2] + b_hh2[g2];
    }

    // update-thread mappings: each update thread covers 4 batch rows b + 4m
    const int u1 = isL1 ? (tid % H1) : 0;
    const int b1 = isL1 ? (tid / H1) : 0;               // 0..3
    const int u2 = isL2 ? ((tid - L2_BASE) % H2) : 0;
    const int b2 = isL2 ? ((tid - L2_BASE) / H2) : 0;
    float c1[4] = {0.0f, 0.0f, 0.0f, 0.0f};
    float c2[4] = {0.0f, 0.0f, 0.0f, 0.0f};

    // ---- x register prefetch: 3 slots, idx = tid + 288*s (NXEL=608) ----
    int xb[3], xk[3];
    bool xv[3];
    #pragma unroll
    for (int s = 0; s < 3; s++) {
        int idx = tid + THREADS * s;
        xv[s] = idx < NXEL;
        int bb = xv[s] ? (idx / I1) : 0;
        xb[s] = bb; xk[s] = xv[s] ? (idx - bb * I1) : 0;
    }
    float xr[3] = {0.0f, 0.0f, 0.0f};

    // ---- prologue: x(0) -> smem buf 0; xr <- x(1) ----
    __syncthreads();   // smem zero done
    #pragma unroll
    for (int s = 0; s < 3; s++) {
        if (xv[s])
            sm.x[0][xb[s]][xk[s]] = x[((long)(bbase + xb[s]) * T_LEN + 0) * I1 + xk[s]];
    }
    #pragma unroll
    for (int s = 0; s < 3; s++) {
        if (xv[s])
            xr[s] = x[((long)(bbase + xb[s]) * T_LEN + 1) * I1 + xk[s]];
    }
    __syncthreads();

    // L2 gate compute (mainloop: step t-1; epilogue: step T-1)
    auto l2_gates = [&]() {
        const int g2 = tid - L2_BASE;
        for (int cb = 0; cb < BB; cb += CHUNK) {       // 2 runtime chunks
            ull acc[CHUNK];
            #pragma unroll
            for (int j = 0; j < CHUNK; j++) acc[j] = pack2(bias, 0.0f);
            #pragma unroll
            for (int k4 = 0; k4 < HP1 / 4; k4++) {     // h1 part
                #pragma unroll
                for (int j = 0; j < CHUNK; j++) {
                    ulonglong2 v = *((const ulonglong2*)&sm.h1[cb + j][4 * k4]);
                    acc[j] = ffma2(v.x, wreg2[2 * k4],     acc[j]);
                    acc[j] = ffma2(v.y, wreg2[2 * k4 + 1], acc[j]);
                }
            }
            #pragma unroll
            for (int k4 = 0; k4 < HP2 / 4; k4++) {     // h2 part
                #pragma unroll
                for (int j = 0; j < CHUNK; j++) {
                    ulonglong2 v = *((const ulonglong2*)&sm.h2[cb + j][4 * k4]);
                    acc[j] = ffma2(v.x, wreg2[HP1 / 2 + 2 * k4],     acc[j]);
                    acc[j] = ffma2(v.y, wreg2[HP1 / 2 + 2 * k4 + 1], acc[j]);
                }
            }
            #pragma unroll
            for (int j = 0; j < CHUNK; j++) {
                float lo, hi; unpack2(acc[j], lo, hi);
                sm.gates2[cb + j][g2] = lo + hi;
            }
        }
    };

    auto l2_update = [&]() {
        #pragma unroll
        for (int m = 0; m < 4; m++) {
            int bb = b2 + 4 * m;
            float ig = sigm(sm.gates2[bb][u2]);
            float fg = sigm(sm.gates2[bb][H2 + u2]);
            float gg = tanh_f(sm.gates2[bb][2 * H2 + u2]);
            float og = sigm(sm.gates2[bb][3 * H2 + u2]);
            c2[m] = fg * c2[m] + ig * gg;
            sm.h2[bb][u2] = og * tanh_f(c2[m]);
        }
    };

    // =================== main recurrence ===================
    for (int t = 0; t < T_LEN; ++t) {
        const int buf = t & 1;

        // ---- top of phase A: commit x(t+1) regs -> smem buf^1 (buffer idle
        //      since last step's barrier), then issue LDG for x(t+2) ----
        if (t + 1 < T_LEN) {
            #pragma unroll
            for (int s = 0; s < 3; s++)
                if (xv[s]) sm.x[buf ^ 1][xb[s]][xk[s]] = xr[s];
        }
        if (t + 2 < T_LEN) {
            #pragma unroll
            for (int s = 0; s < 3; s++)
                if (xv[s])
                    xr[s] = x[((long)(bbase + xb[s]) * T_LEN + (t + 2)) * I1 + xk[s]];
        }

        // ---- Phase A: L1 gates(t) || L2 gates(t-1) ----
        if (isL1) {
            for (int cb = 0; cb < BB; cb += CHUNK) {   // 2 runtime chunks
                ull acc[CHUNK];
                #pragma unroll
                for (int j = 0; j < CHUNK; j++) acc[j] = pack2(bias, 0.0f);
                #pragma unroll
                for (int k4 = 0; k4 < XP / 4; k4++) {  // input part
                    #pragma unroll
                    for (int j = 0; j < CHUNK; j++) {
                        ulonglong2 v = *((const ulonglong2*)&sm.x[buf][cb + j][4 * k4]);
                        acc[j] = ffma2(v.x, wreg2[2 * k4],     acc[j]);
                        acc[j] = ffma2(v.y, wreg2[2 * k4 + 1], acc[j]);
                    }
                }
                #pragma unroll
                for (int k4 = 0; k4 < HP1 / 4; k4++) { // recurrent part
                    #pragma unroll
                    for (int j = 0; j < CHUNK; j++) {
                        ulonglong2 v = *((const ulonglong2*)&sm.h1[cb + j][4 * k4]);
                        acc[j] = ffma2(v.x, wreg2[XP / 2 + 2 * k4],     acc[j]);
                        acc[j] = ffma2(v.y, wreg2[XP / 2 + 2 * k4 + 1], acc[j]);
                    }
                }
                #pragma unroll
                for (int j = 0; j < CHUNK; j++) {
                    float lo, hi; unpack2(acc[j], lo, hi);
                    sm.gates1[cb + j][tid] = lo + hi;
                }
            }
        } else if (isL2 && t > 0) {
            l2_gates();   // step t-1
        }
        __syncthreads();

        // ---- Phase B: L1 update(t) || L2 update(t-1) ----
        if (isL1) {
            #pragma unroll
            for (int m = 0; m < 4; m++) {
                int bb = b1 + 4 * m;
                float ig = sigm(sm.gates1[bb][u1]);
                float fg = sigm(sm.gates1[bb][H1 + u1]);
                float gg = tanh_f(sm.gates1[bb][2 * H1 + u1]);
                float og = sigm(sm.gates1[bb][3 * H1 + u1]);
                c1[m] = fg * c1[m] + ig * gg;
                sm.h1[bb][u1] = og * tanh_f(c1[m]);
            }
        } else if (isL2 && t > 0) {
            l2_update();  // step t-1
        }
        __syncthreads();
    }

    // =================== epilogue: L2 step T-1, then FC ===================
    if (isL2) l2_gates();        // uses h1[T-1], h2[T-2]
    __syncthreads();
    if (isL2) l2_update();       // h2[T-1]
    __syncthreads();

    if (tid < BB * NC) {         // 224 <= 288: single pass
        int bb = tid / NC, nc = tid - bb * NC;
        float s = b_fc[nc];
        #pragma unroll
        for (int k = 0; k < H2; k++) s = fmaf(sm.h2[bb][k], w_fc[nc * H2 + k], s);
        out[(long)(bbase + bb) * NC + nc] = s;
    }
}

extern "C" void kernel_launch(void* const* d_in, const int* in_sizes, int n_in,
                              void* d_out, int out_size)
{
    const float* x     = (const float*)d_in[0];
    const float* w_ih1 = (const float*)d_in[1];
    const float* w_hh1 = (const float*)d_in[2];
    const float* b_ih1 = (const float*)d_in[3];
    const float* b_hh1 = (const float*)d_in[4];
    const float* w_ih2 = (const float*)d_in[5];
    const float* w_hh2 = (const float*)d_in[6];
    const float* b_ih2 = (const float*)d_in[7];
    const float* b_hh2 = (const float*)d_in[8];
    const float* w_fc  = (const float*)d_in[9];
    const float* b_fc  = (const float*)d_in[10];
    float* out = (float*)d_out;

    lstm2_kernel<<<BATCH / BB, THREADS>>>(x, w_ih1, w_hh1, b_ih1, b_hh1,
                                          w_ih2, w_hh2, b_ih2, b_hh2,
                                          w_fc, b_fc, out);
}